// round 1
// baseline (speedup 1.0000x reference)
#include <cuda_runtime.h>
#include <math.h>

// Problem dims
#define BB 4
#define CC 64
#define HH 128
#define WW 128
#define PLANE (HH*WW)
#define CHW (CC*PLANE)
#define TOT (BB*CHW)

// Scratch (allocation-free rule: __device__ globals)
__device__ float g_t0[TOT];
__device__ float g_t1[TOT];
__device__ float g_t2[TOT];
__device__ float g_t3[TOT];
__device__ float g_a[TOT];
__device__ float g_b[TOT];

// e^{-q^2/2} for q=0..7
__constant__ float c_GC[8] = {
    1.0f,
    0.60653065971263342f,
    0.13533528323661270f,
    0.011108996538242306f,
    3.3546262790251185e-4f,
    3.7266531720786709e-6f,
    1.5229979744712628e-8f,
    2.2897348456652846e-11f
};

// ---------------------------------------------------------------------------
// 5x5 conv, 64 output channels. Tile 32x16 px, 128 threads.
// Each thread: 4 pixels (y-strided) x 16 output channels.
// EDGE  : replication pad (forward path)
// !EDGE : zero pad (cropped conv_transpose path)
// TRANS : weight = W[ic][oc][24-t] (transposed+flipped), else W[oc][ic][t]
// ---------------------------------------------------------------------------
template<int ICTOT, bool EDGE, bool TRANS>
__global__ __launch_bounds__(128)
void conv5_kernel(const float* __restrict__ in, const float* __restrict__ Wt,
                  const float* __restrict__ bias, float* __restrict__ out,
                  float inScale)
{
    constexpr int ICC = (ICTOT < 8) ? ICTOT : 8;
    constexpr int NCH = ICTOT / ICC;
    __shared__ float sIn[ICC][20][36];
    __shared__ float sW[16][ICC][25];

    const int tid = threadIdx.x;
    const int tx = blockIdx.x & 3, ty = blockIdx.x >> 2;
    const int x0 = tx * 32, y0 = ty * 16;
    const int ocg = blockIdx.y, b = blockIdx.z;
    const int px = tid & 31, r0 = tid >> 5;

    float acc[64];
#pragma unroll
    for (int i = 0; i < 64; i++) acc[i] = 0.f;

    for (int ch = 0; ch < NCH; ++ch) {
        const int icBase = ch * ICC;
        // input tile (with halo 2)
        for (int idx = tid; idx < ICC * 20 * 36; idx += 128) {
            int xi = idx % 36;
            int rem = idx / 36;
            int yi = rem % 20;
            int ic = rem / 20;
            int gx = x0 + xi - 2, gy = y0 + yi - 2;
            float v;
            if (EDGE) {
                gx = min(max(gx, 0), WW - 1);
                gy = min(max(gy, 0), HH - 1);
                v = in[(((size_t)b * ICTOT + icBase + ic) * HH + gy) * WW + gx];
            } else {
                v = 0.f;
                if (gx >= 0 && gx < WW && gy >= 0 && gy < HH)
                    v = in[(((size_t)b * ICTOT + icBase + ic) * HH + gy) * WW + gx];
            }
            sIn[ic][yi][xi] = v * inScale;
        }
        // weights for this (oc group, ic chunk)
        for (int idx = tid; idx < 16 * ICC * 25; idx += 128) {
            int t = idx % 25;
            int rem = idx / 25;
            int ic = rem % ICC;
            int o = rem / ICC;
            int og = ocg * 16 + o, ig = icBase + ic;
            float w;
            if (TRANS)  // W layout [64][64][25]; out-ch = dim1, flipped taps
                w = Wt[((size_t)ig * 64 + og) * 25 + (24 - t)];
            else        // W layout [64][ICTOT][25]
                w = Wt[((size_t)og * ICTOT + ig) * 25 + t];
            sW[o][ic][t] = w;
        }
        __syncthreads();

        for (int ic = 0; ic < ICC; ++ic) {
            for (int ky = 0; ky < 5; ++ky) {
#pragma unroll
                for (int kx = 0; kx < 5; ++kx) {
                    float v0 = sIn[ic][r0 +      ky][px + kx];
                    float v1 = sIn[ic][r0 + 4  + ky][px + kx];
                    float v2 = sIn[ic][r0 + 8  + ky][px + kx];
                    float v3 = sIn[ic][r0 + 12 + ky][px + kx];
#pragma unroll
                    for (int o = 0; o < 16; ++o) {
                        float w = sW[o][ic][ky * 5 + kx];
                        acc[o * 4 + 0] = fmaf(v0, w, acc[o * 4 + 0]);
                        acc[o * 4 + 1] = fmaf(v1, w, acc[o * 4 + 1]);
                        acc[o * 4 + 2] = fmaf(v2, w, acc[o * 4 + 2]);
                        acc[o * 4 + 3] = fmaf(v3, w, acc[o * 4 + 3]);
                    }
                }
            }
        }
        __syncthreads();
    }

#pragma unroll
    for (int o = 0; o < 16; ++o) {
        const int og = ocg * 16 + o;
        float bv = (bias != nullptr) ? bias[og] : 0.f;
#pragma unroll
        for (int p = 0; p < 4; ++p) {
            int gy = y0 + r0 + p * 4;
            out[(((size_t)b * CC + og) * HH + gy) * WW + x0 + px] = acc[o * 4 + p] + bv;
        }
    }
}

// ---------------------------------------------------------------------------
// RBF mixture activation via shifted-grid factorization.
// means mu_p = -310 + 10 p, p in [0,62], sigma^2 = 100, spacing == sigma.
// exp(-(x-mu_{p0+q})^2/200) = exp(-d^2/200) * exp(qd/10) * exp(-q^2/2)
// window |q| <= 7 is exact to ~1e-11. 3 MUFU exps per value, rest FMA.
// S0 = sum w*term, S1 = sum w*term*q.
//   forward  = S0
//   gradient = (-1/100) * (d*S0 - 10*S1)      [since x - mu_p = d - 10 q]
// ---------------------------------------------------------------------------
__device__ __forceinline__ void act_sums(float v, const float* __restrict__ sw,
                                         float& S0, float& S1, float& dOut)
{
    float u = v * 0.1f + 31.0f;
    float p0f = floorf(u + 0.5f);
    p0f = fminf(fmaxf(p0f, 0.f), 62.f);
    int p0 = (int)p0f;
    float d = v - (p0f * 10.f - 310.f);
    d = fminf(fmaxf(d, -125.f), 125.f);   // keep intermediates representable
    float pref = __expf(d * d * (-1.f / 200.f));
    float r    = __expf(d * 0.1f);
    float ri   = __expf(d * (-0.1f));
    float s0 = sw[p0 + 7] * pref;
    float s1 = 0.f;
    float rp = pref, rm = pref;
#pragma unroll
    for (int q = 1; q <= 7; ++q) {
        rp *= r;
        rm *= ri;
        float g  = c_GC[q];
        float tp = sw[p0 + 7 + q] * (g * rp);
        float tm = sw[p0 + 7 - q] * (g * rm);
        s0 += tp + tm;
        s1 += (float)q * (tp - tm);
    }
    S0 = s0; S1 = s1; dOut = d;
}

__global__ __launch_bounds__(256)
void act_fwd_kernel(const float* __restrict__ tin, const float* __restrict__ actw,
                    float* __restrict__ outp)
{
    __shared__ float sw[80];
    const int c = blockIdx.y, b = blockIdx.z;
    const int tid = threadIdx.x;
    if (tid < 80) sw[tid] = (tid >= 7 && tid < 70) ? actw[c * 63 + tid - 7] : 0.f;
    __syncthreads();
    const float* base = tin  + ((size_t)b * CC + c) * PLANE;
    float*       ob   = outp + ((size_t)b * CC + c) * PLANE;
    int start = blockIdx.x * 2048 + tid;
#pragma unroll
    for (int k = 0; k < 8; ++k) {
        int i = start + k * 256;
        float S0, S1, d;
        act_sums(base[i], sw, S0, S1, d);
        ob[i] = S0;
    }
}

__global__ __launch_bounds__(256)
void act_gradmul_kernel(const float* __restrict__ tin, const float* __restrict__ actw,
                        const float* __restrict__ gin, float* __restrict__ gout)
{
    __shared__ float sw[80];
    const int c = blockIdx.y, b = blockIdx.z;
    const int tid = threadIdx.x;
    if (tid < 80) sw[tid] = (tid >= 7 && tid < 70) ? actw[c * 63 + tid - 7] : 0.f;
    __syncthreads();
    const size_t off = ((size_t)b * CC + c) * PLANE;
    const float* base = tin + off;
    const float* gb   = gin + off;
    float*       ob   = gout + off;
    int start = blockIdx.x * 2048 + tid;
#pragma unroll
    for (int k = 0; k < 8; ++k) {
        int i = start + k * 256;
        float S0, S1, d;
        act_sums(base[i], sw, S0, S1, d);
        float grad = (-0.01f) * (d * S0 - 10.f * S1);
        ob[i] = gb[i] * grad;
    }
}

// ---------------------------------------------------------------------------
// Final: out = x_in - convT0(g)/255 - e^lam * (x_in - y_in)
// convT0: 64 -> 1 channel, zero pad, f0 flipped: w[ic][t] = f0[ic*25 + 24-t]
// ---------------------------------------------------------------------------
__global__ __launch_bounds__(128)
void convt_final_kernel(const float* __restrict__ in, const float* __restrict__ f0,
                        const float* __restrict__ xin, const float* __restrict__ yin,
                        const float* __restrict__ lam, float* __restrict__ outp)
{
    __shared__ float sIn[8][20][36];
    __shared__ float sW[8][25];
    const int tid = threadIdx.x;
    const int tx = blockIdx.x & 3, ty = blockIdx.x >> 2;
    const int x0 = tx * 32, y0 = ty * 16, b = blockIdx.z;
    const int px = tid & 31, r0 = tid >> 5;
    float acc[4] = {0.f, 0.f, 0.f, 0.f};

    for (int ch = 0; ch < 8; ++ch) {
        const int icBase = ch * 8;
        for (int idx = tid; idx < 8 * 20 * 36; idx += 128) {
            int xi = idx % 36;
            int rem = idx / 36;
            int yi = rem % 20;
            int ic = rem / 20;
            int gx = x0 + xi - 2, gy = y0 + yi - 2;
            float v = 0.f;
            if (gx >= 0 && gx < WW && gy >= 0 && gy < HH)
                v = in[(((size_t)b * CC + icBase + ic) * HH + gy) * WW + gx];
            sIn[ic][yi][xi] = v;
        }
        for (int idx = tid; idx < 8 * 25; idx += 128) {
            int t = idx % 25, ic = idx / 25;
            sW[ic][t] = f0[(size_t)(icBase + ic) * 25 + (24 - t)];
        }
        __syncthreads();
        for (int ic = 0; ic < 8; ++ic) {
            for (int ky = 0; ky < 5; ++ky) {
#pragma unroll
                for (int kx = 0; kx < 5; ++kx) {
                    float w = sW[ic][ky * 5 + kx];
                    acc[0] = fmaf(sIn[ic][r0 +      ky][px + kx], w, acc[0]);
                    acc[1] = fmaf(sIn[ic][r0 + 4  + ky][px + kx], w, acc[1]);
                    acc[2] = fmaf(sIn[ic][r0 + 8  + ky][px + kx], w, acc[2]);
                    acc[3] = fmaf(sIn[ic][r0 + 12 + ky][px + kx], w, acc[3]);
                }
            }
        }
        __syncthreads();
    }

    float elam = __expf(lam[0]);
#pragma unroll
    for (int p = 0; p < 4; ++p) {
        int gy = y0 + r0 + p * 4;
        size_t o = ((size_t)b * HH + gy) * WW + x0 + px;
        float xv = xin[o], yv = yin[o];
        outp[o] = xv - acc[p] * (1.f / 255.f) - elam * (xv - yv);
    }
}

// ---------------------------------------------------------------------------
extern "C" void kernel_launch(void* const* d_in, const int* in_sizes, int n_in,
                              void* d_out, int out_size)
{
    const float* x    = (const float*)d_in[0];
    const float* y    = (const float*)d_in[1];
    const float* lam  = (const float*)d_in[2];
    const float* f0   = (const float*)d_in[3];
    const float* fr   = (const float*)d_in[4];
    const float* bias = (const float*)d_in[5];
    const float* actw = (const float*)d_in[6];
    float* out = (float*)d_out;

    float *t0, *t1, *t2, *t3, *a, *b;
    cudaGetSymbolAddress((void**)&t0, g_t0);
    cudaGetSymbolAddress((void**)&t1, g_t1);
    cudaGetSymbolAddress((void**)&t2, g_t2);
    cudaGetSymbolAddress((void**)&t3, g_t3);
    cudaGetSymbolAddress((void**)&a,  g_a);
    cudaGetSymbolAddress((void**)&b,  g_b);

    const dim3 gConv(32, 4, 4), bConv(128);
    const dim3 gAct(8, 64, 4),  bAct(256);
    const size_t FS = 64 * 64 * 25;   // per-layer f_rest stride
    const size_t AS = 64 * 63;        // per-layer actw stride

    // forward diffusion
    conv5_kernel<1,  true, false><<<gConv, bConv>>>(x, f0,          bias + 0,   t0, 255.f);
    act_fwd_kernel<<<gAct, bAct>>>(t0, actw + 0 * AS, a);
    conv5_kernel<64, true, false><<<gConv, bConv>>>(a, fr + 0 * FS, bias + 64,  t1, 1.f);
    act_fwd_kernel<<<gAct, bAct>>>(t1, actw + 1 * AS, a);
    conv5_kernel<64, true, false><<<gConv, bConv>>>(a, fr + 1 * FS, bias + 128, t2, 1.f);
    act_fwd_kernel<<<gAct, bAct>>>(t2, actw + 2 * AS, a);
    conv5_kernel<64, true, false><<<gConv, bConv>>>(a, fr + 2 * FS, bias + 192, t3, 1.f);
    act_fwd_kernel<<<gAct, bAct>>>(t3, actw + 3 * AS, a);

    // backward diffusion
    conv5_kernel<64, false, true><<<gConv, bConv>>>(a, fr + 2 * FS, nullptr, b, 1.f);
    act_gradmul_kernel<<<gAct, bAct>>>(t2, actw + 2 * AS, b, a);
    conv5_kernel<64, false, true><<<gConv, bConv>>>(a, fr + 1 * FS, nullptr, b, 1.f);
    act_gradmul_kernel<<<gAct, bAct>>>(t1, actw + 1 * AS, b, a);
    conv5_kernel<64, false, true><<<gConv, bConv>>>(a, fr + 0 * FS, nullptr, b, 1.f);
    act_gradmul_kernel<<<gAct, bAct>>>(t0, actw + 0 * AS, b, a);

    // final 64->1 transposed conv fused with output combine
    convt_final_kernel<<<dim3(32, 1, 4), 128>>>(a, f0, x, y, lam, out);
}